// round 1
// baseline (speedup 1.0000x reference)
#include <cuda_runtime.h>

// ---------------- constants ----------------
#define IMG   224
#define OUT1  112
#define OUT2  56
#define BATCH 32
#define NPIX1 (OUT1*OUT1)   // 12544
#define NPIX2 (OUT2*OUT2)   // 3136
#define N1F   401408.0f     // 32*112*112
#define N2F   100352.0f     // 32*56*56

// ---------------- scratch (__device__ globals; no alloc allowed) ----------------
__device__ float g_out1[BATCH*128*NPIX1];   // 205 MB pre-BN conv1 output
__device__ float g_h[BATCH*128*NPIX2];      // 51 MB post-pool
__device__ float g_w1t[147*128];            // conv1 weights [k][oc]
__device__ float g_w2t[1152*128];           // conv2 weights [k][oc]
__device__ int   g_win[28*8];               // per (s,w): ti,li,to,lo,oh,ow,fh,fw
__device__ float g_sum1[128], g_sq1[128], g_sum2[128], g_sq2[128];
__device__ float g_a1[128], g_b1[128], g_a2[128], g_b2[128];

// ---------------- f32x2 helpers ----------------
__device__ __forceinline__ unsigned long long fma2(unsigned long long a,
                                                   unsigned long long b,
                                                   unsigned long long c) {
    unsigned long long d;
    asm("fma.rn.f32x2 %0, %1, %2, %3;" : "=l"(d) : "l"(a), "l"(b), "l"(c));
    return d;
}
__device__ __forceinline__ unsigned long long dup2(float x) {
    unsigned long long d;
    asm("mov.b64 %0, {%1, %2};" : "=l"(d) : "f"(x), "f"(x));
    return d;
}
__device__ __forceinline__ unsigned long long pk2(float lo, float hi) {
    unsigned long long d;
    asm("mov.b64 %0, {%1, %2};" : "=l"(d) : "f"(lo), "f"(hi));
    return d;
}
__device__ __forceinline__ float2 up2(unsigned long long v) {
    float2 r;
    asm("mov.b64 {%0, %1}, %2;" : "=f"(r.x), "=f"(r.y) : "l"(v));
    return r;
}

// ---------------- init: window table, weight transposes, zero stats ----------------
__global__ void k_init(const float* __restrict__ w1, const float* __restrict__ w2) {
    int tid = blockIdx.x * blockDim.x + threadIdx.x;
    if (tid < 128) { g_sum1[tid] = 0.f; g_sq1[tid] = 0.f; g_sum2[tid] = 0.f; g_sq2[tid] = 0.f; }
    if (tid < 147*128) {            // w1t[k][oc] = w1[oc][k]
        int k = tid >> 7, oc = tid & 127;
        g_w1t[tid] = w1[oc*147 + k];
    }
    if (tid < 1152*128) {           // w2t[k][oc] = w2[oc][k]
        int kk = tid >> 7, oc = tid & 127;
        g_w2t[tid] = w2[oc*1152 + kk];
    }
    if (blockIdx.x == 0 && threadIdx.x < 28) {
        int s = threadIdx.x >> 2, w = threadIdx.x & 3;
        int a = 16*s, b = a + 16, c = 224 - b, d = 224 - a;
        int t, l, bt, r;
        if      (w == 0) { t = a; l = a; bt = b; r = c; }
        else if (w == 1) { t = b; l = a; bt = d; r = b; }
        else if (w == 2) { t = c; l = b; bt = d; r = d; }
        else             { t = a; l = c; bt = c; r = d; }
        float scale = (float)(2.0 - (double)s / 6.0);   // numpy linspace(2,1,7) value
        int ti = (int)__fdiv_rn((float)(t  + 6), scale) - 3;
        int li = (int)__fdiv_rn((float)(l  + 6), scale) - 3;
        int bi = (int)__fdiv_rn((float)(bt + 6), scale) + 3;
        int ri = (int)__fdiv_rn((float)(r  + 6), scale) + 3;
        int to = t >> 1, lo = l >> 1;
        int oh = (bt >> 1) - to, oww = (r >> 1) - lo;
        int fh = (bi - ti - 7) / 2 + 1, fw = (ri - li - 7) / 2 + 1;
        int* p = g_win + threadIdx.x * 8;
        p[0]=ti; p[1]=li; p[2]=to; p[3]=lo; p[4]=oh; p[5]=oww; p[6]=fh; p[7]=fw;
    }
}

// ---------------- conv1: multi-scale 7x7 s2 conv, 8x8 output tile x 128 oc ----------------
// dyn smem: patch 147*64 floats + weight chunk 49*128 floats = 62.7 KB
__global__ void __launch_bounds__(256) k_conv1(const float* __restrict__ inp) {
    extern __shared__ float smem[];
    float* s_patch = smem;            // [147][64]
    float* s_w     = smem + 147*64;   // [49][128] (k-chunked)
    __shared__ int   s_iy0[64], s_ix0[64];
    __shared__ float s_red[256];      // [0:128) sum, [128:256) sumsq

    int tid = threadIdx.x;
    int n = blockIdx.z;
    int bi_ = blockIdx.y, bj_ = blockIdx.x;
    int y0 = bi_ * 8, x0 = bj_ * 8;

    int s = min(min(bi_, bj_), min(13 - bi_, 13 - bj_));
    int b2 = 8 * (s + 1), c2 = 112 - b2;
    int w;
    if (y0 < b2 && x0 < c2) w = 0;
    else if (x0 < b2)       w = 1;
    else if (y0 >= c2)      w = 2;
    else                    w = 3;
    const int* wp = g_win + (s * 4 + w) * 8;
    int ti = wp[0], li = wp[1], to = wp[2], lo = wp[3];
    int oh = wp[4], oww = wp[5], fh = wp[6], fw = wp[7];

    s_red[tid] = 0.f;
    if (tid < 64) {
        int py = y0 + (tid >> 3), px = x0 + (tid & 7);
        s_iy0[tid] = ti + 2 * (((py - to) * fh) / oh)  - 3;
        s_ix0[tid] = li + 2 * (((px - lo) * fw) / oww) - 3;
    }
    __syncthreads();

    // gather per-pixel 7x7x3 patches (zero-padded)
    const float* inN = inp + n * 3 * IMG * IMG;
    for (int idx = tid; idx < 147 * 64; idx += 256) {
        int k = idx >> 6, pi = idx & 63;
        int c  = k / 49, rem = k - c * 49;
        int ky = rem / 7, kx = rem - ky * 7;
        int iy = s_iy0[pi] + ky, ix = s_ix0[pi] + kx;
        float v = 0.f;
        if ((unsigned)iy < 224u && (unsigned)ix < 224u)
            v = __ldg(inN + (c * 224 + iy) * 224 + ix);
        s_patch[idx] = v;
    }

    int ocb = tid & 31, py = tid >> 5;
    const float* pb = s_patch + py * 8;
    const float* wb = s_w + (ocb << 2);

    unsigned long long acc[4][4];
    #pragma unroll
    for (int o = 0; o < 4; o++)
        #pragma unroll
        for (int p = 0; p < 4; p++) acc[o][p] = 0ull;

    for (int c3 = 0; c3 < 3; c3++) {           // k chunks of 49
        __syncthreads();
        {   // stage weight chunk [49][128]
            const float4* src = (const float4*)(g_w1t + c3 * 49 * 128);
            float4* dst = (float4*)s_w;
            #pragma unroll 2
            for (int idx = tid; idx < 49 * 32; idx += 256) dst[idx] = src[idx];
        }
        __syncthreads();
        const float* pc = pb + c3 * 49 * 64;
        #pragma unroll 7
        for (int k = 0; k < 49; k++) {
            ulonglong2 pA = *(const ulonglong2*)(pc + k * 64);
            ulonglong2 pB = *(const ulonglong2*)(pc + k * 64 + 4);
            float4 wv = *(const float4*)(wb + k * 128);
            unsigned long long wd[4] = { dup2(wv.x), dup2(wv.y), dup2(wv.z), dup2(wv.w) };
            #pragma unroll
            for (int o = 0; o < 4; o++) {
                acc[o][0] = fma2(wd[o], pA.x, acc[o][0]);
                acc[o][1] = fma2(wd[o], pA.y, acc[o][1]);
                acc[o][2] = fma2(wd[o], pB.x, acc[o][2]);
                acc[o][3] = fma2(wd[o], pB.y, acc[o][3]);
            }
        }
    }

    // epilogue: store + fused BN1 stats
    int yy = y0 + py;
    #pragma unroll
    for (int o = 0; o < 4; o++) {
        int oc = (ocb << 2) + o;
        float2 f0 = up2(acc[o][0]), f1 = up2(acc[o][1]);
        float2 f2 = up2(acc[o][2]), f3 = up2(acc[o][3]);
        float4 v0 = make_float4(f0.x, f0.y, f1.x, f1.y);
        float4 v1 = make_float4(f2.x, f2.y, f3.x, f3.y);
        float* dst = g_out1 + ((n * 128 + oc) * 112 + yy) * 112 + x0;
        *(float4*)dst       = v0;
        *(float4*)(dst + 4) = v1;
        float sm = f0.x + f0.y + f1.x + f1.y + f2.x + f2.y + f3.x + f3.y;
        float sq = f0.x*f0.x + f0.y*f0.y + f1.x*f1.x + f1.y*f1.y
                 + f2.x*f2.x + f2.y*f2.y + f3.x*f3.x + f3.y*f3.y;
        atomicAdd(&s_red[oc], sm);
        atomicAdd(&s_red[128 + oc], sq);
    }
    __syncthreads();
    if (tid < 128) {
        atomicAdd(&g_sum1[tid], s_red[tid]);
        atomicAdd(&g_sq1[tid],  s_red[128 + tid]);
    }
}

// ---------------- BN finalize ----------------
__global__ void k_fin1(const float* __restrict__ gamma, const float* __restrict__ beta) {
    int c = threadIdx.x;
    float mean = g_sum1[c] * (1.f / N1F);
    float var  = g_sq1[c]  * (1.f / N1F) - mean * mean;
    float a = gamma[c] * rsqrtf(var + 1e-5f);
    g_a1[c] = a; g_b1[c] = beta[c] - a * mean;
}
__global__ void k_fin2(const float* __restrict__ gamma, const float* __restrict__ beta) {
    int c = threadIdx.x;
    float mean = g_sum2[c] * (1.f / N2F);
    float var  = g_sq2[c]  * (1.f / N2F) - mean * mean;
    float a = gamma[c] * rsqrtf(var + 1e-5f);
    g_a2[c] = a; g_b2[c] = beta[c] - a * mean;
}

// ---------------- BN1 + ReLU + 3x3 s2 p1 maxpool ----------------
__global__ void k_pool() {
    int idx = blockIdx.x * 256 + threadIdx.x;
    if (idx >= BATCH * 128 * NPIX2) return;
    int x  = idx % 56;
    int y  = (idx / 56) % 56;
    int nc = idx / NPIX2;
    int c  = nc & 127;
    float a = g_a1[c], b = g_b1[c];
    const float* src = g_out1 + nc * NPIX1;
    float m = -1e30f;
    #pragma unroll
    for (int dy = 0; dy < 3; dy++) {
        int yy = 2 * y - 1 + dy;
        if ((unsigned)yy >= 112u) continue;
        #pragma unroll
        for (int dx = 0; dx < 3; dx++) {
            int xx = 2 * x - 1 + dx;
            if ((unsigned)xx >= 112u) continue;
            m = fmaxf(m, fmaf(a, src[yy * 112 + xx], b));
        }
    }
    g_h[idx] = fmaxf(m, 0.f);
}

// ---------------- conv2: 3x3 p1 s1, 128->128, 8x8 tile x 128 oc ----------------
// dyn smem: patch 16*10*12 + weights 144*128 = 79.5 KB
__global__ void __launch_bounds__(256) k_conv2(float* __restrict__ out) {
    extern __shared__ float smem[];
    float* s_patch = smem;          // [16][10][12]
    float* s_w     = smem + 1920;   // [144][128]
    __shared__ float s_red[256];

    int tid = threadIdx.x;
    int n = blockIdx.z, y0 = blockIdx.y * 8, x0 = blockIdx.x * 8;
    int ocb = tid & 31, py = tid >> 5;

    s_red[tid] = 0.f;

    unsigned long long acc[4][4];
    #pragma unroll
    for (int o = 0; o < 4; o++)
        #pragma unroll
        for (int p = 0; p < 4; p++) acc[o][p] = 0ull;

    for (int ic0 = 0; ic0 < 128; ic0 += 16) {
        __syncthreads();
        // stage input patch chunk [16][10][10] (zero-padded halo)
        for (int idx = tid; idx < 1600; idx += 256) {
            int ic = idx / 100, rem = idx - ic * 100;
            int r = rem / 10, cl = rem - r * 10;
            int gy = y0 + r - 1, gx = x0 + cl - 1;
            float v = 0.f;
            if ((unsigned)gy < 56u && (unsigned)gx < 56u)
                v = g_h[((n * 128 + ic0 + ic) * 56 + gy) * 56 + gx];
            s_patch[(ic * 10 + r) * 12 + cl] = v;
        }
        // stage weight chunk [144][128]
        {
            const float4* src = (const float4*)(g_w2t + ic0 * 9 * 128);
            float4* dst = (float4*)s_w;
            #pragma unroll 2
            for (int idx = tid; idx < 144 * 32; idx += 256) dst[idx] = src[idx];
        }
        __syncthreads();

        #pragma unroll 2
        for (int ic = 0; ic < 16; ic++) {
            #pragma unroll
            for (int ky = 0; ky < 3; ky++) {
                const float* prow = s_patch + (ic * 10 + py + ky) * 12;
                float4 r0 = *(const float4*)(prow);
                float4 r1 = *(const float4*)(prow + 4);
                float4 r2 = *(const float4*)(prow + 8);
                float rr[12] = { r0.x, r0.y, r0.z, r0.w,
                                 r1.x, r1.y, r1.z, r1.w,
                                 r2.x, r2.y, r2.z, r2.w };
                #pragma unroll
                for (int kx = 0; kx < 3; kx++) {
                    float4 wv = *(const float4*)(s_w + (ic * 9 + ky * 3 + kx) * 128 + (ocb << 2));
                    unsigned long long wd[4] = { dup2(wv.x), dup2(wv.y), dup2(wv.z), dup2(wv.w) };
                    unsigned long long p0 = pk2(rr[kx    ], rr[kx + 1]);
                    unsigned long long p1 = pk2(rr[kx + 2], rr[kx + 3]);
                    unsigned long long p2 = pk2(rr[kx + 4], rr[kx + 5]);
                    unsigned long long p3 = pk2(rr[kx + 6], rr[kx + 7]);
                    #pragma unroll
                    for (int o = 0; o < 4; o++) {
                        acc[o][0] = fma2(wd[o], p0, acc[o][0]);
                        acc[o][1] = fma2(wd[o], p1, acc[o][1]);
                        acc[o][2] = fma2(wd[o], p2, acc[o][2]);
                        acc[o][3] = fma2(wd[o], p3, acc[o][3]);
                    }
                }
            }
        }
    }

    // epilogue: store pre-BN conv2 to d_out + fused BN2 stats
    int yy = y0 + py;
    #pragma unroll
    for (int o = 0; o < 4; o++) {
        int oc = (ocb << 2) + o;
        float2 f0 = up2(acc[o][0]), f1 = up2(acc[o][1]);
        float2 f2 = up2(acc[o][2]), f3 = up2(acc[o][3]);
        float4 v0 = make_float4(f0.x, f0.y, f1.x, f1.y);
        float4 v1 = make_float4(f2.x, f2.y, f3.x, f3.y);
        float* dst = out + ((n * 128 + oc) * 56 + yy) * 56 + x0;
        *(float4*)dst       = v0;
        *(float4*)(dst + 4) = v1;
        float sm = f0.x + f0.y + f1.x + f1.y + f2.x + f2.y + f3.x + f3.y;
        float sq = f0.x*f0.x + f0.y*f0.y + f1.x*f1.x + f1.y*f1.y
                 + f2.x*f2.x + f2.y*f2.y + f3.x*f3.x + f3.y*f3.y;
        atomicAdd(&s_red[oc], sm);
        atomicAdd(&s_red[128 + oc], sq);
    }
    __syncthreads();
    if (tid < 128) {
        atomicAdd(&g_sum2[tid], s_red[tid]);
        atomicAdd(&g_sq2[tid],  s_red[128 + tid]);
    }
}

// ---------------- BN2 + ReLU in place on d_out ----------------
__global__ void k_bn2(float* __restrict__ out) {
    int idx = blockIdx.x * 256 + threadIdx.x;
    if (idx >= BATCH * 128 * NPIX2) return;
    int c = (idx / NPIX2) & 127;
    out[idx] = fmaxf(fmaf(g_a2[c], out[idx], g_b2[c]), 0.f);
}

// ---------------- launch ----------------
extern "C" void kernel_launch(void* const* d_in, const int* in_sizes, int n_in,
                              void* d_out, int out_size) {
    const float* inp = (const float*)d_in[0];
    const float* w1  = (const float*)d_in[1];
    const float* g1  = (const float*)d_in[2];
    const float* b1  = (const float*)d_in[3];
    const float* w2  = (const float*)d_in[4];
    const float* g2  = (const float*)d_in[5];
    const float* b2  = (const float*)d_in[6];
    float* out = (float*)d_out;

    const int smem1 = (147*64 + 49*128) * 4;     // 62.7 KB
    const int smem2 = (1920 + 144*128) * 4;      // 81.4 KB... wait: 1920+18432 = 20352 floats
    cudaFuncSetAttribute(k_conv1, cudaFuncAttributeMaxDynamicSharedMemorySize, smem1);
    cudaFuncSetAttribute(k_conv2, cudaFuncAttributeMaxDynamicSharedMemorySize, smem2);

    k_init<<<576, 256>>>(w1, w2);
    k_conv1<<<dim3(14, 14, BATCH), 256, smem1>>>(inp);
    k_fin1<<<1, 128>>>(g1, b1);
    k_pool<<<(BATCH*128*NPIX2 + 255) / 256, 256>>>();
    k_conv2<<<dim3(7, 7, BATCH), 256, smem2>>>(out);
    k_fin2<<<1, 128>>>(g2, b2);
    k_bn2<<<(BATCH*128*NPIX2 + 255) / 256, 256>>>(out);
}

// round 3
// speedup vs baseline: 1.2100x; 1.2100x over previous
#include <cuda_runtime.h>
#include <cuda_bf16.h>
#include <cstdint>

// ---------------- constants ----------------
#define IMG   224
#define BATCH 32
#define NPIX1 12544
#define NPIX2 3136
#define N1F   401408.0f
#define N2F   100352.0f

// GEMM smem geometry: rows of 32 bf16 (64B) padded to 80B stride
#define RSTRIDE 80
#define ATERM   10240          // 128 rows * 80B (one term, one operand)
#define BOFF    20480          // B starts after A(hi)+A(lo)
#define STAGEB  40960          // full stage: Ah,Al,Bh,Bl
#define DYN     81920          // two stages

// ---------------- scratch ----------------
__device__ float g_out1[BATCH*128*NPIX1];
__device__ float g_h[BATCH*128*NPIX2];
__device__ __nv_bfloat16 g_w1bh[128*160], g_w1bl[128*160];
__device__ __nv_bfloat16 g_w2bh[128*1152], g_w2bl[128*1152];
__device__ int   g_win[28*8];
__device__ float g_sum1[128], g_sq1[128], g_sum2[128], g_sq2[128];
__device__ float g_a1[128], g_b1[128], g_a2[128], g_b2[128];

// ---------------- helpers ----------------
__device__ __forceinline__ uint32_t smem_u32(const void* p) {
    uint32_t a;
    asm("{ .reg .u64 t; cvta.to.shared.u64 t, %1; cvt.u32.u64 %0, t; }" : "=r"(a) : "l"(p));
    return a;
}
__device__ __forceinline__ void ldsm4(uint32_t addr, uint32_t* r) {
    asm volatile("ldmatrix.sync.aligned.m8n8.x4.shared.b16 {%0,%1,%2,%3}, [%4];"
        : "=r"(r[0]), "=r"(r[1]), "=r"(r[2]), "=r"(r[3]) : "r"(addr));
}
__device__ __forceinline__ void mma16816(float* c, const uint32_t* a, const uint32_t* b) {
    asm volatile("mma.sync.aligned.m16n8k16.row.col.f32.bf16.bf16.f32 "
        "{%0,%1,%2,%3}, {%4,%5,%6,%7}, {%8,%9}, {%0,%1,%2,%3};"
        : "+f"(c[0]), "+f"(c[1]), "+f"(c[2]), "+f"(c[3])
        : "r"(a[0]), "r"(a[1]), "r"(a[2]), "r"(a[3]), "r"(b[0]), "r"(b[1]));
}
__device__ __forceinline__ uint32_t bfpack(float v0, float v1, uint32_t& lo) {
    __nv_bfloat16 h0 = __float2bfloat16(v0);
    __nv_bfloat16 h1 = __float2bfloat16(v1);
    __nv_bfloat16 l0 = __float2bfloat16(v0 - __bfloat162float(h0));
    __nv_bfloat16 l1 = __float2bfloat16(v1 - __bfloat162float(h1));
    lo = ((uint32_t)__bfloat16_as_ushort(l1) << 16) | (uint32_t)__bfloat16_as_ushort(l0);
    return ((uint32_t)__bfloat16_as_ushort(h1) << 16) | (uint32_t)__bfloat16_as_ushort(h0);
}

// one K=32 chunk of bf16x3 MMA for a 64x32 warp tile
__device__ __forceinline__ void mma_stage(uint32_t Ab, uint32_t Bb,
                                          uint32_t Aln, uint32_t Bln,
                                          float (*acc)[4][4]) {
    #pragma unroll
    for (int h = 0; h < 2; h++) {
        uint32_t ab = Ab + h*32 + Aln;
        uint32_t bb = Bb + h*32 + Bln;
        uint32_t ah[4][4], bq[4][2], bl[4][2], t[4];
        #pragma unroll
        for (int mt = 0; mt < 4; mt++) ldsm4(ab + mt*(16*RSTRIDE), ah[mt]);
        #pragma unroll
        for (int nh = 0; nh < 2; nh++) {
            ldsm4(bb + nh*(16*RSTRIDE), t);
            bq[nh*2][0] = t[0]; bq[nh*2][1] = t[1];
            bq[nh*2+1][0] = t[2]; bq[nh*2+1][1] = t[3];
        }
        #pragma unroll
        for (int mt = 0; mt < 4; mt++)
            #pragma unroll
            for (int nt = 0; nt < 4; nt++) mma16816(acc[mt][nt], ah[mt], bq[nt]);
        #pragma unroll
        for (int nh = 0; nh < 2; nh++) {
            ldsm4(bb + ATERM + nh*(16*RSTRIDE), t);
            bl[nh*2][0] = t[0]; bl[nh*2][1] = t[1];
            bl[nh*2+1][0] = t[2]; bl[nh*2+1][1] = t[3];
        }
        #pragma unroll
        for (int mt = 0; mt < 4; mt++)
            #pragma unroll
            for (int nt = 0; nt < 4; nt++) mma16816(acc[mt][nt], ah[mt], bl[nt]);
        #pragma unroll
        for (int mt = 0; mt < 4; mt++) ldsm4(ab + ATERM + mt*(16*RSTRIDE), ah[mt]);
        #pragma unroll
        for (int mt = 0; mt < 4; mt++)
            #pragma unroll
            for (int nt = 0; nt < 4; nt++) mma16816(acc[mt][nt], ah[mt], bq[nt]);
    }
}

// staging macros (shared by both conv kernels)
#define LDGA(s) do { _Pragma("unroll") \
    for (int i = 0; i < 4; i++) areg[i] = *(const uint4*)(asrc[i] + (s)*32); } while (0)
#define STSA(buf) do { _Pragma("unroll") \
    for (int i = 0; i < 4; i++) *(uint4*)(dsm + (buf)*STAGEB + asts[i]) = areg[i]; } while (0)
#define STSB(buf) do { \
    uint32_t hw[8], lw[8]; \
    _Pragma("unroll") \
    for (int j = 0; j < 8; j++) hw[j] = bfpack(breg[2*j], breg[2*j+1], lw[j]); \
    char* bp = dsm + (buf)*STAGEB + BOFF + (tid>>1)*RSTRIDE + khalf*32; \
    *(uint4*)bp        = make_uint4(hw[0], hw[1], hw[2], hw[3]); \
    *(uint4*)(bp + 16) = make_uint4(hw[4], hw[5], hw[6], hw[7]); \
    *(uint4*)(bp + ATERM)      = make_uint4(lw[0], lw[1], lw[2], lw[3]); \
    *(uint4*)(bp + ATERM + 16) = make_uint4(lw[4], lw[5], lw[6], lw[7]); } while (0)

// ---------------- init ----------------
__global__ void k_init(const float* __restrict__ w1, const float* __restrict__ w2) {
    int tid = blockIdx.x * blockDim.x + threadIdx.x;
    if (tid < 128) { g_sum1[tid] = 0.f; g_sq1[tid] = 0.f; g_sum2[tid] = 0.f; g_sq2[tid] = 0.f; }
    if (tid < 128*160) {
        int oc = tid / 160, k = tid - oc*160;
        float v = (k < 147) ? w1[oc*147 + k] : 0.f;
        __nv_bfloat16 h = __float2bfloat16(v);
        g_w1bh[tid] = h;
        g_w1bl[tid] = __float2bfloat16(v - __bfloat162float(h));
    }
    if (tid < 128*1152) {
        float v = w2[tid];
        __nv_bfloat16 h = __float2bfloat16(v);
        g_w2bh[tid] = h;
        g_w2bl[tid] = __float2bfloat16(v - __bfloat162float(h));
    }
    if (blockIdx.x == 0 && threadIdx.x < 28) {
        int s = threadIdx.x >> 2, w = threadIdx.x & 3;
        int a = 16*s, b = a + 16, c = 224 - b, d = 224 - a;
        int t, l, bt, r;
        if      (w == 0) { t = a; l = a; bt = b; r = c; }
        else if (w == 1) { t = b; l = a; bt = d; r = b; }
        else if (w == 2) { t = c; l = b; bt = d; r = d; }
        else             { t = a; l = c; bt = c; r = d; }
        float scale = (float)(2.0 - (double)s / 6.0);
        int ti = (int)__fdiv_rn((float)(t  + 6), scale) - 3;
        int li = (int)__fdiv_rn((float)(l  + 6), scale) - 3;
        int bi = (int)__fdiv_rn((float)(bt + 6), scale) + 3;
        int ri = (int)__fdiv_rn((float)(r  + 6), scale) + 3;
        int to = t >> 1, lo = l >> 1;
        int oh = (bt >> 1) - to, oww = (r >> 1) - lo;
        int fh = (bi - ti - 7) / 2 + 1, fw = (ri - li - 7) / 2 + 1;
        int* p = g_win + threadIdx.x * 8;
        p[0]=ti; p[1]=li; p[2]=to; p[3]=lo; p[4]=oh; p[5]=oww; p[6]=fh; p[7]=fw;
    }
}

// ---------------- conv1: bf16x3 mma implicit GEMM (M=128 oc, K=160 pad, N=128 px tiles) ----------------
__global__ void __launch_bounds__(256, 1) k_conv1m(const float* __restrict__ inp) {
    extern __shared__ char dsm[];
    __shared__ int s_win[224];
    __shared__ int t_c[160];
    __shared__ signed char t_ky[160], t_kx[160];
    __shared__ float s_red[256];

    int tid = threadIdx.x, lane = tid & 31, wid = tid >> 5;
    int warp_m = wid >> 2, warp_n = wid & 3;

    if (tid < 224) s_win[tid] = g_win[tid];
    if (tid < 160) {
        int k = tid;
        if (k < 147) {
            int c = k / 49, r = k - c*49, ky = r / 7, kx = r - ky*7;
            t_c[k] = c * 50176; t_ky[k] = (signed char)ky; t_kx[k] = (signed char)kx;
        } else { t_c[k] = -1; t_ky[k] = 0; t_kx[k] = 0; }
    }
    s_red[tid] = 0.f;
    __syncthreads();

    int img = blockIdx.x / 98;
    int pixbase = (blockIdx.x - img*98) * 128;
    int pix = pixbase + (tid >> 1);
    int y = pix / 112, x = pix - y*112;
    int khalf = tid & 1;

    // per-pixel window
    int bi = y >> 3, bj = x >> 3;
    int sS = min(min(bi, bj), min(13 - bi, 13 - bj));
    int b2 = 8 * (sS + 1), c2v = 112 - b2;
    int w = (y < b2 && x < c2v) ? 0 : (x < b2 ? 1 : (y >= c2v ? 2 : 3));
    const int* wp = s_win + (sS*4 + w)*8;
    int ti = wp[0], li = wp[1], to = wp[2], lo = wp[3];
    int oh = wp[4], oww = wp[5], fh = wp[6], fw = wp[7];
    int iy0 = ti + 2 * (((y - to) * fh) / oh)  - 3;
    int ix0 = li + 2 * (((x - lo) * fw) / oww) - 3;
    const float* ibase = inp + img * 150528;

    // A staging descriptors
    uint4 areg[4]; float breg[16];
    const __nv_bfloat16* asrc[4]; uint32_t asts[4];
    #pragma unroll
    for (int i = 0; i < 4; i++) {
        int id = tid + i*256, term = id >> 9, rem = id & 511, row = rem >> 2, c = rem & 3;
        asrc[i] = (term ? g_w1bl : g_w1bh) + row*160 + c*8;
        asts[i] = term*ATERM + row*RSTRIDE + c*16;
    }

    uint32_t sb = smem_u32(dsm);
    uint32_t Aln = (lane & 15)*RSTRIDE + (lane >> 4)*16;
    uint32_t Bln = ((lane >> 4)*8 + (lane & 7))*RSTRIDE + ((lane >> 3) & 1)*16;

    #define C1_LDGB(s) do { int kb = (s)*32 + khalf*16; \
        _Pragma("unroll") for (int j = 0; j < 16; j++) { \
            int k = kb + j; \
            int iy = iy0 + t_ky[k], ix = ix0 + t_kx[k]; \
            bool v = (t_c[k] >= 0) && ((unsigned)iy < 224u) && ((unsigned)ix < 224u); \
            breg[j] = v ? __ldg(ibase + t_c[k] + iy*224 + ix) : 0.f; } } while (0)

    float acc[4][4][4];
    #pragma unroll
    for (int a = 0; a < 4; a++)
        #pragma unroll
        for (int b = 0; b < 4; b++)
            #pragma unroll
            for (int c = 0; c < 4; c++) acc[a][b][c] = 0.f;

    LDGA(0); C1_LDGB(0); STSA(0); STSB(0);
    __syncthreads();
    for (int s = 0; s < 5; s++) {
        int buf = s & 1;
        if (s < 4) { LDGA(s + 1); C1_LDGB(s + 1); }
        mma_stage(sb + buf*STAGEB + warp_m*(64*RSTRIDE),
                  sb + buf*STAGEB + BOFF + warp_n*(32*RSTRIDE), Aln, Bln, acc);
        if (s < 4) { STSA(buf ^ 1); STSB(buf ^ 1); }
        __syncthreads();
    }

    // epilogue: store + BN1 stats
    int g = lane >> 2, cp = (lane & 3) * 2;
    #pragma unroll
    for (int mt = 0; mt < 4; mt++) {
        #pragma unroll
        for (int hh = 0; hh < 2; hh++) {
            int oc = warp_m*64 + mt*16 + hh*8 + g;
            float sv = 0.f, qv = 0.f;
            float* obase = g_out1 + (size_t)(img*128 + oc)*NPIX1;
            #pragma unroll
            for (int nt = 0; nt < 4; nt++) {
                float c0 = acc[mt][nt][hh*2], c1 = acc[mt][nt][hh*2 + 1];
                int pxl = warp_n*32 + nt*8 + cp;
                float2 v2 = make_float2(c0, c1);
                *(float2*)(obase + pixbase + pxl) = v2;
                sv += c0 + c1; qv += c0*c0 + c1*c1;
            }
            atomicAdd(&s_red[oc], sv);
            atomicAdd(&s_red[128 + oc], qv);
        }
    }
    __syncthreads();
    if (tid < 128) {
        atomicAdd(&g_sum1[tid], s_red[tid]);
        atomicAdd(&g_sq1[tid],  s_red[128 + tid]);
    }
}

// ---------------- BN finalize ----------------
__global__ void k_fin1(const float* __restrict__ gamma, const float* __restrict__ beta) {
    int c = threadIdx.x;
    float mean = g_sum1[c] * (1.f / N1F);
    float var  = g_sq1[c]  * (1.f / N1F) - mean * mean;
    float a = gamma[c] * rsqrtf(var + 1e-5f);
    g_a1[c] = a; g_b1[c] = beta[c] - a * mean;
}
__global__ void k_fin2(const float* __restrict__ gamma, const float* __restrict__ beta) {
    int c = threadIdx.x;
    float mean = g_sum2[c] * (1.f / N2F);
    float var  = g_sq2[c]  * (1.f / N2F) - mean * mean;
    float a = gamma[c] * rsqrtf(var + 1e-5f);
    g_a2[c] = a; g_b2[c] = beta[c] - a * mean;
}

// ---------------- BN1 + ReLU + 3x3 s2 p1 maxpool ----------------
__global__ void k_pool() {
    int idx = blockIdx.x * 256 + threadIdx.x;
    if (idx >= BATCH * 128 * NPIX2) return;
    int x  = idx % 56;
    int y  = (idx / 56) % 56;
    int nc = idx / NPIX2;
    int c  = nc & 127;
    float a = g_a1[c], b = g_b1[c];
    const float* src = g_out1 + (size_t)nc * NPIX1;
    float m = -1e30f;
    #pragma unroll
    for (int dy = 0; dy < 3; dy++) {
        int yy = 2*y - 1 + dy;
        if ((unsigned)yy >= 112u) continue;
        #pragma unroll
        for (int dx = 0; dx < 3; dx++) {
            int xx = 2*x - 1 + dx;
            if ((unsigned)xx >= 112u) continue;
            m = fmaxf(m, fmaf(a, src[yy*112 + xx], b));
        }
    }
    g_h[idx] = fmaxf(m, 0.f);
}

// ---------------- conv2: bf16x3 mma implicit GEMM (M=128 oc, K=1152, N=128 px tiles) ----------------
__global__ void __launch_bounds__(256, 1) k_conv2m(float* __restrict__ out) {
    extern __shared__ char dsm[];
    __shared__ int t_off[1152];
    __shared__ signed char t_dy[1152], t_dx[1152];
    __shared__ float s_red[256];

    int tid = threadIdx.x, lane = tid & 31, wid = tid >> 5;
    int warp_m = wid >> 2, warp_n = wid & 3;

    for (int k = tid; k < 1152; k += 256) {
        int ic = k / 9, r = k - ic*9, dy = r/3 - 1, dx = r - (r/3)*3 - 1;
        t_off[k] = ic*3136 + dy*56 + dx;
        t_dy[k] = (signed char)dy; t_dx[k] = (signed char)dx;
    }
    s_red[tid] = 0.f;
    __syncthreads();

    int pxg = blockIdx.x*128 + (tid >> 1);
    int img = pxg / 3136, pix = pxg - img*3136;
    int y = pix / 56, x = pix - y*56;
    int khalf = tid & 1;
    const float* hbase = g_h + (size_t)img*(128*3136) + pix;
    bool oky[3] = { y > 0, true, y < 55 };
    bool okx[3] = { x > 0, true, x < 55 };

    uint4 areg[4]; float breg[16];
    const __nv_bfloat16* asrc[4]; uint32_t asts[4];
    #pragma unroll
    for (int i = 0; i < 4; i++) {
        int id = tid + i*256, term = id >> 9, rem = id & 511, row = rem >> 2, c = rem & 3;
        asrc[i] = (term ? g_w2bl : g_w2bh) + row*1152 + c*8;
        asts[i] = term*ATERM + row*RSTRIDE + c*16;
    }

    uint32_t sb = smem_u32(dsm);
    uint32_t Aln = (lane & 15)*RSTRIDE + (lane >> 4)*16;
    uint32_t Bln = ((lane >> 4)*8 + (lane & 7))*RSTRIDE + ((lane >> 3) & 1)*16;

    #define C2_LDGB(s) do { int kb = (s)*32 + khalf*16; \
        _Pragma("unroll") for (int j = 0; j < 16; j++) { \
            int k = kb + j; \
            bool v = oky[t_dy[k] + 1] && okx[t_dx[k] + 1]; \
            breg[j] = v ? __ldg(hbase + t_off[k]) : 0.f; } } while (0)

    float acc[4][4][4];
    #pragma unroll
    for (int a = 0; a < 4; a++)
        #pragma unroll
        for (int b = 0; b < 4; b++)
            #pragma unroll
            for (int c = 0; c < 4; c++) acc[a][b][c] = 0.f;

    LDGA(0); C2_LDGB(0); STSA(0); STSB(0);
    __syncthreads();
    for (int s = 0; s < 36; s++) {
        int buf = s & 1;
        if (s < 35) { LDGA(s + 1); C2_LDGB(s + 1); }
        mma_stage(sb + buf*STAGEB + warp_m*(64*RSTRIDE),
                  sb + buf*STAGEB + BOFF + warp_n*(32*RSTRIDE), Aln, Bln, acc);
        if (s < 35) { STSA(buf ^ 1); STSB(buf ^ 1); }
        __syncthreads();
    }

    // epilogue: store pre-BN + BN2 stats
    int g = lane >> 2, cp = (lane & 3) * 2;
    #pragma unroll
    for (int mt = 0; mt < 4; mt++) {
        #pragma unroll
        for (int hh = 0; hh < 2; hh++) {
            int oc = warp_m*64 + mt*16 + hh*8 + g;
            float sv = 0.f, qv = 0.f;
            #pragma unroll
            for (int nt = 0; nt < 4; nt++) {
                float c0 = acc[mt][nt][hh*2], c1 = acc[mt][nt][hh*2 + 1];
                int pxl = warp_n*32 + nt*8 + cp;
                int pg = blockIdx.x*128 + pxl;
                int im2 = pg / 3136, pi2 = pg - im2*3136;
                float2 v2 = make_float2(c0, c1);
                *(float2*)(out + (size_t)(im2*128 + oc)*3136 + pi2) = v2;
                sv += c0 + c1; qv += c0*c0 + c1*c1;
            }
            atomicAdd(&s_red[oc], sv);
            atomicAdd(&s_red[128 + oc], qv);
        }
    }
    __syncthreads();
    if (tid < 128) {
        atomicAdd(&g_sum2[tid], s_red[tid]);
        atomicAdd(&g_sq2[tid],  s_red[128 + tid]);
    }
}

// ---------------- BN2 + ReLU in place on d_out ----------------
__global__ void k_bn2(float* __restrict__ out) {
    int idx = blockIdx.x * 256 + threadIdx.x;
    if (idx >= BATCH * 128 * NPIX2) return;
    int c = (idx / NPIX2) & 127;
    out[idx] = fmaxf(fmaf(g_a2[c], out[idx], g_b2[c]), 0.f);
}

// ---------------- launch ----------------
extern "C" void kernel_launch(void* const* d_in, const int* in_sizes, int n_in,
                              void* d_out, int out_size) {
    const float* inp = (const float*)d_in[0];
    const float* w1  = (const float*)d_in[1];
    const float* g1  = (const float*)d_in[2];
    const float* b1  = (const float*)d_in[3];
    const float* w2  = (const float*)d_in[4];
    const float* g2  = (const float*)d_in[5];
    const float* b2  = (const float*)d_in[6];
    float* out = (float*)d_out;

    cudaFuncSetAttribute(k_conv1m, cudaFuncAttributeMaxDynamicSharedMemorySize, DYN);
    cudaFuncSetAttribute(k_conv2m, cudaFuncAttributeMaxDynamicSharedMemorySize, DYN);

    k_init<<<576, 256>>>(w1, w2);
    k_conv1m<<<3136, 256, DYN>>>(inp);
    k_fin1<<<1, 128>>>(g1, b1);
    k_pool<<<(BATCH*128*NPIX2 + 255) / 256, 256>>>();
    k_conv2m<<<784, 256, DYN>>>(out);
    k_fin2<<<1, 128>>>(g2, b2);
    k_bn2<<<(BATCH*128*NPIX2 + 255) / 256, 256>>>(out);
}